// round 9
// baseline (speedup 1.0000x reference)
#include <cuda_runtime.h>

#define NN 256
#define CC 64
#define TT 64
#define VV 25
#define SS 3
#define RR 8
#define OO 64
#define HH 16
#define KK 75   // S*V contraction length

// ---- scratch ----
__device__ float g_xm[NN * CC * VV];
__device__ float g_m[NN * SS * OO * VV * VV];            // [n][s][o][v][u]
__device__ float g_x3[(size_t)NN * OO * KK * TT];        // [n][o][k][t]  (t fastest)
__device__ float g_y[NN * OO * TT * VV];                 // [n][o][t][u]
__device__ float g_sea[NN * OO];
__device__ float g_seb[NN * OO];

// ============================================================
// K0: dummy (keeps k3a at the profiler's captured launch index)
// ============================================================
__global__ void k0_dummy() {}

// ============================================================
// K1: xm[n,c,v] = mean over T
// ============================================================
__global__ void k1_mean(const float* __restrict__ x) {
    int idx = blockIdx.x * 256 + threadIdx.x;
    if (idx >= NN * CC * VV) return;
    int v  = idx % VV;
    int nc = idx / VV;
    const float* p = x + (size_t)nc * (TT * VV) + v;
    float s = 0.f;
#pragma unroll
    for (int t = 0; t < TT; ++t) s += p[t * VV];
    g_xm[idx] = s * (1.0f / TT);
}

// ============================================================
// K2: attention map + softmax. CTA per (n,s), 256 threads.
// ============================================================
__global__ void k2_attn(const float* __restrict__ PA, const float* __restrict__ alpha,
                        const float* __restrict__ w1, const float* __restrict__ b1,
                        const float* __restrict__ w2, const float* __restrict__ b2,
                        const float* __restrict__ w4, const float* __restrict__ b4) {
    int n = blockIdx.x / SS, s = blockIdx.x % SS;
    int tid = threadIdx.x;

    __shared__ float xms[CC * VV];
    __shared__ float x1s[RR * VV];
    __shared__ float x2s[RR * VV];
    __shared__ float atts[RR * VV * VV];

    for (int i = tid; i < CC * VV; i += 256) xms[i] = g_xm[n * CC * VV + i];
    __syncthreads();

    for (int i2 = tid; i2 < 2 * RR * VV; i2 += 256) {
        int which = i2 / (RR * VV);
        int i = i2 % (RR * VV);
        int r = i / VV, u = i % VV;
        const float* w = (which ? w2 : w1) + (s * RR + r) * CC;
        float acc = (which ? b2 : b1)[s * RR + r];
#pragma unroll
        for (int c = 0; c < CC; ++c) acc += w[c] * xms[c * VV + u];
        (which ? x2s : x1s)[i] = acc;
    }
    __syncthreads();

    for (int i = tid; i < RR * VV * VV; i += 256) {
        int r = i / (VV * VV); int rem = i % (VV * VV);
        int u = rem / VV, v = rem % VV;
        atts[i] = tanhf(x1s[r * VV + u] - x2s[r * VV + v]);
    }
    __syncthreads();

    float al = alpha[s];
    for (int pos = tid; pos < OO * VV; pos += 256) {
        int o = pos / VV, v = pos % VV;
        float wr[RR];
#pragma unroll
        for (int r = 0; r < RR; ++r) wr[r] = w4[(s * OO + o) * RR + r];
        float b4v = b4[s * OO + o];
        float col[VV];
        float mx = -1e30f;
#pragma unroll
        for (int u = 0; u < VV; ++u) {
            float acc = b4v;
#pragma unroll
            for (int r = 0; r < RR; ++r) acc += wr[r] * atts[r * VV * VV + u * VV + v];
            float val = al * acc + PA[(s * VV + u) * VV + v] + PA[(s * VV + v) * VV + u];
            col[u] = val;
            mx = fmaxf(mx, val);
        }
        float ssum = 0.f;
#pragma unroll
        for (int u = 0; u < VV; ++u) { col[u] = __expf(col[u] - mx); ssum += col[u]; }
        float inv = 1.0f / ssum;
        float* outp = g_m + (((size_t)(n * SS + s) * OO + o) * VV + v) * VV;
#pragma unroll
        for (int u = 0; u < VV; ++u) outp[u] = col[u] * inv;
    }
}

// ============================================================
// K3a: x3[n,o,s*25+v,t] = b3[s,o] + sum_c w3[s,o,c] x[n,c,t,v]
// CTA = (n, s, t-chunk of 8). 256 threads = (o-pair:32, t:8).
// c-split staging (32 c per pass, 45.3KB smem) + v-split accumulators
// (<=26 live accs) -> 4 CTAs/SM at 64 regs, no spills.
// ============================================================
#define TCH 8
#define XSP 28
#define CSP 32
__global__ void __launch_bounds__(256, 4)
k3a_x3(const float* __restrict__ x, const float* __restrict__ w3,
       const float* __restrict__ b3) {
    int bid = blockIdx.x;
    int n = bid / (SS * (TT / TCH));
    int rem = bid % (SS * (TT / TCH));
    int s = rem / (TT / TCH);
    int t0 = (rem % (TT / TCH)) * TCH;
    int tid = threadIdx.x;
    int o0 = (tid >> 3) * 2;
    int t = tid & 7;

    __shared__ float w3s[OO * 65];            // 16.6KB, conflict-free
    __shared__ float x_s[CSP * TCH * XSP];    // 28.7KB

    for (int i = tid; i < OO * CC; i += 256) {
        int oo2 = i >> 6, c = i & 63;
        w3s[oo2 * 65 + c] = w3[s * OO * CC + i];
    }

    float bb0 = b3[s * OO + o0];
    float bb1 = b3[s * OO + o0 + 1];
    float* outp0 = g_x3 + ((size_t)(n * OO + o0) * KK + s * VV) * TT + t0 + t;
    float* outp1 = outp0 + (size_t)KK * TT;

    // ---------- half 0: v in [0,12) ----------
    {
        float a0[12], a1[12];
#pragma unroll
        for (int v = 0; v < 12; ++v) { a0[v] = bb0; a1[v] = bb1; }

#pragma unroll 1
        for (int cs = 0; cs < 2; ++cs) {
            __syncthreads();
            for (int j = tid; j < CSP * TCH * VV; j += 256) {
                int c = j / (TCH * VV);
                int tv = j % (TCH * VV);
                int tl = tv / VV, v = tv % VV;
                x_s[c * (TCH * XSP) + tl * XSP + v] =
                    x[((size_t)(n * CC + cs * CSP + c) * TT + (t0 + tl)) * VV + v];
            }
            __syncthreads();
#pragma unroll 4
            for (int c = 0; c < CSP; ++c) {
                float wv0 = w3s[o0 * 65 + cs * CSP + c];
                float wv1 = w3s[(o0 + 1) * 65 + cs * CSP + c];
                const float* xr = x_s + c * (TCH * XSP) + t * XSP;
#pragma unroll
                for (int v4 = 0; v4 < 3; ++v4) {
                    float4 q = *(const float4*)(xr + v4 * 4);
                    a0[v4 * 4 + 0] = fmaf(wv0, q.x, a0[v4 * 4 + 0]);
                    a0[v4 * 4 + 1] = fmaf(wv0, q.y, a0[v4 * 4 + 1]);
                    a0[v4 * 4 + 2] = fmaf(wv0, q.z, a0[v4 * 4 + 2]);
                    a0[v4 * 4 + 3] = fmaf(wv0, q.w, a0[v4 * 4 + 3]);
                    a1[v4 * 4 + 0] = fmaf(wv1, q.x, a1[v4 * 4 + 0]);
                    a1[v4 * 4 + 1] = fmaf(wv1, q.y, a1[v4 * 4 + 1]);
                    a1[v4 * 4 + 2] = fmaf(wv1, q.z, a1[v4 * 4 + 2]);
                    a1[v4 * 4 + 3] = fmaf(wv1, q.w, a1[v4 * 4 + 3]);
                }
            }
        }
#pragma unroll
        for (int v = 0; v < 12; ++v) {
            outp0[v * TT] = a0[v];
            outp1[v * TT] = a1[v];
        }
    }

    // ---------- half 1: v in [12,25) ----------
    {
        float a0[13], a1[13];
#pragma unroll
        for (int v = 0; v < 13; ++v) { a0[v] = bb0; a1[v] = bb1; }

#pragma unroll 1
        for (int cs = 0; cs < 2; ++cs) {
            __syncthreads();
            for (int j = tid; j < CSP * TCH * VV; j += 256) {
                int c = j / (TCH * VV);
                int tv = j % (TCH * VV);
                int tl = tv / VV, v = tv % VV;
                x_s[c * (TCH * XSP) + tl * XSP + v] =
                    x[((size_t)(n * CC + cs * CSP + c) * TT + (t0 + tl)) * VV + v];
            }
            __syncthreads();
#pragma unroll 4
            for (int c = 0; c < CSP; ++c) {
                float wv0 = w3s[o0 * 65 + cs * CSP + c];
                float wv1 = w3s[(o0 + 1) * 65 + cs * CSP + c];
                const float* xr = x_s + c * (TCH * XSP) + t * XSP + 12;
#pragma unroll
                for (int v4 = 0; v4 < 3; ++v4) {
                    float4 q = *(const float4*)(xr + v4 * 4);
                    a0[v4 * 4 + 0] = fmaf(wv0, q.x, a0[v4 * 4 + 0]);
                    a0[v4 * 4 + 1] = fmaf(wv0, q.y, a0[v4 * 4 + 1]);
                    a0[v4 * 4 + 2] = fmaf(wv0, q.z, a0[v4 * 4 + 2]);
                    a0[v4 * 4 + 3] = fmaf(wv0, q.w, a0[v4 * 4 + 3]);
                    a1[v4 * 4 + 0] = fmaf(wv1, q.x, a1[v4 * 4 + 0]);
                    a1[v4 * 4 + 1] = fmaf(wv1, q.y, a1[v4 * 4 + 1]);
                    a1[v4 * 4 + 2] = fmaf(wv1, q.z, a1[v4 * 4 + 2]);
                    a1[v4 * 4 + 3] = fmaf(wv1, q.w, a1[v4 * 4 + 3]);
                }
                float xt = xr[12];
                a0[12] = fmaf(wv0, xt, a0[12]);
                a1[12] = fmaf(wv1, xt, a1[12]);
            }
        }
#pragma unroll
        for (int v = 0; v < 13; ++v) {
            outp0[(v + 12) * TT] = a0[v];
            outp1[(v + 12) * TT] = a1[v];
        }
    }
}

// ============================================================
// K3b: y[n,o,t,u] = sum_k x3[n,o,k,t] m[n,o,k,u]
// CTA per (n,o). 64 threads = t.
// ============================================================
__global__ void __launch_bounds__(64)
k3b_y() {
    int n = blockIdx.x >> 6, o = blockIdx.x & 63;
    int t = threadIdx.x;

    __shared__ float m_s[KK * 28];            // 8.4KB (reused as y stage)

    for (int i = t; i < SS * VV * VV; i += 64) {
        int s = i / (VV * VV);
        int vu = i % (VV * VV);
        m_s[(s * VV + vu / VV) * 28 + (vu % VV)] =
            g_m[((size_t)(n * SS + s) * OO + o) * (VV * VV) + vu];
    }
    __syncthreads();

    float acc[VV];
#pragma unroll
    for (int u = 0; u < VV; ++u) acc[u] = 0.f;

    const float* xp = g_x3 + (size_t)(n * OO + o) * (KK * TT) + t;

#pragma unroll 5
    for (int k = 0; k < KK; ++k) {
        float xx = __ldg(xp + k * TT);
        const float* mr = m_s + k * 28;
#pragma unroll
        for (int u4 = 0; u4 < 6; ++u4) {
            float4 q = *(const float4*)(mr + u4 * 4);
            acc[u4 * 4 + 0] = fmaf(xx, q.x, acc[u4 * 4 + 0]);
            acc[u4 * 4 + 1] = fmaf(xx, q.y, acc[u4 * 4 + 1]);
            acc[u4 * 4 + 2] = fmaf(xx, q.z, acc[u4 * 4 + 2]);
            acc[u4 * 4 + 3] = fmaf(xx, q.w, acc[u4 * 4 + 3]);
        }
        acc[24] = fmaf(xx, mr[24], acc[24]);
    }

    __syncthreads();
    float* yst = m_s;
#pragma unroll
    for (int u = 0; u < VV; ++u) yst[t * VV + u] = acc[u];
    __syncthreads();
    {
        float4* dst = (float4*)(g_y + (size_t)(n * OO + o) * (TT * VV));
        const float4* src = (const float4*)yst;
        for (int i = t; i < TT * VV / 4; i += 64) dst[i] = src[i];
    }
}

// ============================================================
// K4: BN + SE -> per-(n,o) affine
// ============================================================
__global__ void k4_se(const float* __restrict__ bn_w, const float* __restrict__ bn_b,
                      const float* __restrict__ se_w1, const float* __restrict__ se_b1,
                      const float* __restrict__ se_w2, const float* __restrict__ se_b2) {
    int n = blockIdx.x;
    int tid = threadIdx.x;
    int o = tid >> 2, j = tid & 3;

    const float4* py = (const float4*)(g_y + (size_t)n * OO * TT * VV + o * TT * VV + j * 400);
    float s0 = 0, s1 = 0, s2 = 0, s3 = 0;
#pragma unroll 4
    for (int k = 0; k < 100; ++k) {
        float4 q = py[k];
        s0 += q.x; s1 += q.y; s2 += q.z; s3 += q.w;
    }
    __shared__ float part[256];
    part[tid] = (s0 + s1) + (s2 + s3);
    __syncthreads();

    __shared__ float pool[OO];
    __shared__ float hbuf[HH];
    if (j == 0) {
        float tot = part[tid] + part[tid + 1] + part[tid + 2] + part[tid + 3];
        float g = bn_w[o] * rsqrtf(1.0f + 1e-5f);
        pool[o] = g * (tot * (1.0f / (TT * VV))) + bn_b[o];
    }
    __syncthreads();
    if (tid < HH) {
        float acc = se_b1[tid];
#pragma unroll
        for (int oo2 = 0; oo2 < OO; ++oo2) acc += pool[oo2] * se_w1[tid * OO + oo2];
        hbuf[tid] = fmaxf(acc, 0.f);
    }
    __syncthreads();
    if (tid < OO) {
        float acc = se_b2[tid];
#pragma unroll
        for (int jj = 0; jj < HH; ++jj) acc += hbuf[jj] * se_w2[tid * HH + jj];
        float se = 1.0f / (1.0f + __expf(-acc));
        float g = bn_w[tid] * rsqrtf(1.0f + 1e-5f);
        g_sea[n * OO + tid] = g * se;
        g_seb[n * OO + tid] = bn_b[tid] * se;
    }
}

// ============================================================
// K5: out = relu(y * sea + seb + x)
// ============================================================
__global__ void k5_final(const float* __restrict__ x, float* __restrict__ out) {
    int i4 = blockIdx.x * 256 + threadIdx.x;
    if (i4 >= NN * OO * TT * VV / 4) return;
    int no = i4 / 400;
    float a = g_sea[no], b = g_seb[no];
    float4 y4 = ((const float4*)g_y)[i4];
    float4 x4 = ((const float4*)x)[i4];
    float4 r;
    r.x = fmaxf(fmaf(y4.x, a, b) + x4.x, 0.f);
    r.y = fmaxf(fmaf(y4.y, a, b) + x4.y, 0.f);
    r.z = fmaxf(fmaf(y4.z, a, b) + x4.z, 0.f);
    r.w = fmaxf(fmaf(y4.w, a, b) + x4.w, 0.f);
    ((float4*)out)[i4] = r;
}

// ============================================================
extern "C" void kernel_launch(void* const* d_in, const int* in_sizes, int n_in,
                              void* d_out, int out_size) {
    const float* x     = (const float*)d_in[0];
    const float* PA    = (const float*)d_in[1];
    const float* alpha = (const float*)d_in[2];
    const float* w1    = (const float*)d_in[3];
    const float* b1    = (const float*)d_in[4];
    const float* w2    = (const float*)d_in[5];
    const float* b2    = (const float*)d_in[6];
    const float* w3    = (const float*)d_in[7];
    const float* b3    = (const float*)d_in[8];
    const float* w4    = (const float*)d_in[9];
    const float* b4    = (const float*)d_in[10];
    const float* bn_w  = (const float*)d_in[11];
    const float* bn_b  = (const float*)d_in[12];
    const float* se_w1 = (const float*)d_in[13];
    const float* se_b1 = (const float*)d_in[14];
    const float* se_w2 = (const float*)d_in[15];
    const float* se_b2 = (const float*)d_in[16];
    float* out = (float*)d_out;

    k1_mean<<<(NN * CC * VV + 255) / 256, 256>>>(x);               // idx 0
    k2_attn<<<NN * SS, 256>>>(PA, alpha, w1, b1, w2, b2, w4, b4);  // idx 1
    k0_dummy<<<1, 32>>>();                                          // idx 2
    k3a_x3<<<NN * SS * (TT / TCH), 256>>>(x, w3, b3);               // idx 3 (captured)
    k3b_y<<<NN * OO, 64>>>();
    k4_se<<<NN, 256>>>(bn_w, bn_b, se_w1, se_b1, se_w2, se_b2);
    k5_final<<<(NN * OO * TT * VV / 4 + 255) / 256, 256>>>(x, out);
}